// round 8
// baseline (speedup 1.0000x reference)
#include <cuda_runtime.h>

// CapsuleConv2d fused, round 6: 2 pos/thread + f-split across warps -> 4 CTAs/SM.
// N=4, C=64, H=W=32, O=8, L=16, G=8, P=8, F=72, Ho=Wo=32, NUM_ITERS=3.
// CTA 128 thr = 16 l x 2 ph x 2 wp x 2 fh; covers 8 positions; thread: 2 pos x 36 f.
// grid = (512 tiles, 8 o).
//
// Shared (floats), phase-overlaid, total 13856 = 54.1 KB:
//  phase 1: w_s  [72 f][16 l][2 slot] f4, slot ^ ((l>>2)&1)  @0     (9216)
//           win_s[8 pos](580)[72 f][8 p]                     @9216  (4640)
//  phase 2: spri [8 pos](1456)[72 f](20)[16 l]               @0     (11648)
//           sprob[8 pos](80)[2 fh][40]                       @11648 (640)
//           souts[8 pos][16 l]                               @12288 (128)
//           sacc [2 buf][2 fh][8 pos][16 l]                  @12416 (512)
#define W_S_OFF     0
#define WIN_OFF     9216
#define WIN_STRIDE  580
#define SPRI_OFF    0
#define SPRI_POS    1456
#define SPRI_F      20
#define SPROB_OFF   11648
#define SPROB_POS   80
#define SOUT_OFF    12288
#define SACC_OFF    12416
#define SM_FLOATS   13856

__device__ __forceinline__ float dot4(float4 a, float4 b) {
    return a.x * b.x + a.y * b.y + a.z * b.z + a.w * b.w;
}

__global__ __launch_bounds__(128, 4)
void caps_kernel(const float* __restrict__ x, const float* __restrict__ w,
                 float* __restrict__ out)
{
    extern __shared__ float sm[];
    float* w_s   = sm + W_S_OFF;
    float* win_s = sm + WIN_OFF;
    float* spri  = sm + SPRI_OFF;
    float* sprob = sm + SPROB_OFF;
    float* souts = sm + SOUT_OFF;
    float* sacc  = sm + SACC_OFF;

    const int tid = threadIdx.x;
    const int l   = tid & 15;
    const int ph  = (tid >> 4) & 1;
    const int wp  = (tid >> 5) & 1;
    const int fh  = tid >> 6;            // f-half: 0 -> f 0..35, 1 -> f 36..71
    const int posA = 4 * wp + ph;
    const int posB = posA + 2;
    const int f0   = fh * 36;

    const int o    = blockIdx.y;
    const int tile = blockIdx.x;         // 0..511
    const int n    = tile >> 7;
    const int rem  = tile & 127;
    const int y    = rem >> 2;
    const int x0   = (rem & 3) << 3;

    // ---- phase 1a: stage weights (float4, slot swizzle) ----
    {
        const float4* gw = (const float4*)(w + o * 9216);   // 2304 float4s
        float4* sw = (float4*)w_s;
        #pragma unroll
        for (int i = 0; i < 18; i++) {
            int idx = tid + i * 128;
            int f   = idx >> 5;
            int r   = idx & 31;
            int ll  = r >> 1;
            int s   = r & 1;
            sw[f * 32 + ll * 2 + (s ^ ((ll >> 2) & 1))] = gw[idx];
        }
    }
    // ---- phase 1b: stage win patches; thread -> (ppos, p, g-half) ----
    {
        const int ppos = tid & 7;
        const int p    = (tid >> 3) & 7;
        const int gh   = tid >> 6;          // 4 g each
        const int xb   = x0 + ppos - 1;
        bool py[3], px[3];
        #pragma unroll
        for (int k = 0; k < 3; k++) {
            py[k] = (unsigned)(y + k - 1) < 32u;
            px[k] = (unsigned)(xb + k) < 32u;
        }
        const float* xpb = x + ((n * 64 + gh * 32 + p) * 32 + (y - 1)) * 32 + xb;
        float* wd = win_s + ppos * WIN_STRIDE + p + gh * 4 * 9 * 8;
        #pragma unroll
        for (int g = 0; g < 4; g++) {
            #pragma unroll
            for (int kh = 0; kh < 3; kh++) {
                #pragma unroll
                for (int kw = 0; kw < 3; kw++) {
                    float v = 0.0f;
                    if (py[kh] & px[kw])
                        v = xpb[g * 8192 + kh * 32 + kw];
                    wd[(g * 9 + kh * 3 + kw) * 8] = v;
                }
            }
        }
    }
    __syncthreads();

    // ---- phase 1c: priors for both positions, own f-half ----
    float pa[36], pb[36];
    {
        const int b = (l >> 2) & 1;
        const float4* wlo4 = (const float4*)w_s + l * 2 + b;
        const float4* whi4 = (const float4*)w_s + l * 2 + (1 ^ b);
        const float4* xa4  = (const float4*)win_s + posA * (WIN_STRIDE / 4);
        const float4* xb4  = (const float4*)win_s + posB * (WIN_STRIDE / 4);
        #pragma unroll
        for (int f = 0; f < 36; f++) {
            const int F = f0 + f;
            float4 a0 = wlo4[F * 32];
            float4 a1 = whi4[F * 32];
            float4 A0 = xa4[F * 2], A1 = xa4[F * 2 + 1];
            float4 B0 = xb4[F * 2], B1 = xb4[F * 2 + 1];
            pa[f] = dot4(a0, A0) + dot4(a1, A1);
            pb[f] = dot4(a0, B0) + dot4(a1, B1);
        }
    }

    // ---- phase boundary ----
    __syncthreads();

    {
        float* prA = spri + posA * SPRI_POS + l;
        float* prB = spri + posB * SPRI_POS + l;
        #pragma unroll
        for (int f = 0; f < 36; f++) {
            prA[(f0 + f) * SPRI_F] = pa[f];
            prB[(f0 + f) * SPRI_F] = pb[f];
        }
    }
    __syncwarp();

    // ---- phase 2: routing. probs in owner regs (3 per pos) ----
    float pA0 = 1.0f, pA1 = 1.0f, pA2 = 1.0f;
    float pB0 = 1.0f, pB1 = 1.0f, pB2 = 1.0f;
    float outA = 0.0f, outB = 0.0f;
    #pragma unroll
    for (int r = 0; r < 3; r++) {
        float accA = 0.0f, accB = 0.0f;
        if (r == 0) {
            #pragma unroll
            for (int f = 0; f < 36; f++) { accA += pa[f]; accB += pb[f]; }
        } else {
            const float4* prA4 = (const float4*)(sprob + posA * SPROB_POS + fh * 40);
            const float4* prB4 = (const float4*)(sprob + posB * SPROB_POS + fh * 40);
            #pragma unroll
            for (int i = 0; i < 9; i++) {
                float4 qa = prA4[i];
                float4 qb = prB4[i];
                accA += qa.x * pa[4*i] + qa.y * pa[4*i+1] + qa.z * pa[4*i+2] + qa.w * pa[4*i+3];
                accB += qb.x * pb[4*i] + qb.y * pb[4*i+1] + qb.z * pb[4*i+2] + qb.w * pb[4*i+3];
            }
        }
        // combine f-halves across the two fh warps
        const int buf = (r & 1) * 512 / 2;   // 0 or 256
        sacc[buf + fh * 128 + posA * 16 + l] = accA;
        sacc[buf + fh * 128 + posB * 16 + l] = accB;
        __syncthreads();
        accA += sacc[buf + (1 - fh) * 128 + posA * 16 + l];
        accB += sacc[buf + (1 - fh) * 128 + posB * 16 + l];

        float sA = accA * 0.125f, sB = accB * 0.125f;
        float sqA = sA * sA, sqB = sB * sB;
        #pragma unroll
        for (int d = 8; d >= 1; d >>= 1) {
            sqA += __shfl_xor_sync(0xffffffffu, sqA, d);
            sqB += __shfl_xor_sync(0xffffffffu, sqB, d);
        }
        outA = sA * (sqrtf(sqA) / (1.0f + sqA));
        outB = sB * (sqrtf(sqB) / (1.0f + sqB));

        if (r < 2) {
            // both fh warps write identical values -> no cross-warp barrier needed
            souts[posA * 16 + l] = outA;
            souts[posB * 16 + l] = outB;
            __syncwarp();
            const float4* svA = (const float4*)(souts + posA * 16);
            const float4* svB = (const float4*)(souts + posB * 16);
            float4 a0 = svA[0], a1 = svA[1], a2 = svA[2], a3 = svA[3];
            float4 b0 = svB[0], b1 = svB[1], b2 = svB[2], b3 = svB[3];
            // owner lanes: local f = 16j + l (j=2 only l<4)
            #pragma unroll
            for (int j = 0; j < 3; j++) {
                if (j < 2 || l < 4) {
                    const int fl = 16 * j + l;        // local f index
                    const int F  = f0 + fl;           // global f row
                    const float4* qpA = (const float4*)(spri + posA * SPRI_POS + F * SPRI_F);
                    float dA = dot4(qpA[0], a0) + dot4(qpA[1], a1)
                             + dot4(qpA[2], a2) + dot4(qpA[3], a3);
                    float eA = __expf(dA);
                    float nA;
                    if (j == 0)      { pA0 += eA; nA = pA0; }
                    else if (j == 1) { pA1 += eA; nA = pA1; }
                    else             { pA2 += eA; nA = pA2; }
                    sprob[posA * SPROB_POS + fh * 40 + fl] = nA;

                    const float4* qpB = (const float4*)(spri + posB * SPRI_POS + F * SPRI_F);
                    float dB = dot4(qpB[0], b0) + dot4(qpB[1], b1)
                             + dot4(qpB[2], b2) + dot4(qpB[3], b3);
                    float eB = __expf(dB);
                    float nB;
                    if (j == 0)      { pB0 += eB; nB = pB0; }
                    else if (j == 1) { pB1 += eB; nB = pB1; }
                    else             { pB2 += eB; nB = pB2; }
                    sprob[posB * SPROB_POS + fh * 40 + fl] = nB;
                }
            }
            __syncwarp();
        }
    }

    if (fh == 0) {
        float* ob = out + ((n * 128 + o * 16 + l) * 32 + y) * 32 + x0;
        ob[posA] = outA;
        ob[posB] = outB;
    }
}

extern "C" void kernel_launch(void* const* d_in, const int* in_sizes, int n_in,
                              void* d_out, int out_size)
{
    (void)in_sizes; (void)n_in; (void)out_size;
    const float* x = (const float*)d_in[0];
    const float* w = (const float*)d_in[1];
    float* out     = (float*)d_out;

    cudaFuncSetAttribute(caps_kernel, cudaFuncAttributeMaxDynamicSharedMemorySize,
                         SM_FLOATS * 4);
    dim3 grid(512, 8);
    caps_kernel<<<grid, 128, SM_FLOATS * 4>>>(x, w, out);
}

// round 9
// speedup vs baseline: 1.0116x; 1.0116x over previous
#include <cuda_runtime.h>

// CapsuleConv2d fused, round 6: 2 pos/thread + f-split across warps -> 4 CTAs/SM.
// N=4, C=64, H=W=32, O=8, L=16, G=8, P=8, F=72, Ho=Wo=32, NUM_ITERS=3.
// CTA 128 thr = 16 l x 2 ph x 2 wp x 2 fh; covers 8 positions; thread: 2 pos x 36 f.
// grid = (512 tiles, 8 o).
//
// Shared (floats), phase-overlaid, total 13856 = 54.1 KB:
//  phase 1: w_s  [72 f][16 l][2 slot] f4, slot ^ ((l>>2)&1)  @0     (9216)
//           win_s[8 pos](580)[72 f][8 p]                     @9216  (4640)
//  phase 2: spri [8 pos](1456)[72 f](20)[16 l]               @0     (11648)
//           sprob[8 pos](80)[2 fh][40]                       @11648 (640)
//           souts[8 pos][16 l]                               @12288 (128)
//           sacc [2 buf][2 fh][8 pos][16 l]                  @12416 (512)
#define W_S_OFF     0
#define WIN_OFF     9216
#define WIN_STRIDE  580
#define SPRI_OFF    0
#define SPRI_POS    1456
#define SPRI_F      20
#define SPROB_OFF   11648
#define SPROB_POS   80
#define SOUT_OFF    12288
#define SACC_OFF    12416
#define SM_FLOATS   13856

__device__ __forceinline__ float dot4(float4 a, float4 b) {
    return a.x * b.x + a.y * b.y + a.z * b.z + a.w * b.w;
}

__global__ __launch_bounds__(128, 4)
void caps_kernel(const float* __restrict__ x, const float* __restrict__ w,
                 float* __restrict__ out)
{
    extern __shared__ float sm[];
    float* w_s   = sm + W_S_OFF;
    float* win_s = sm + WIN_OFF;
    float* spri  = sm + SPRI_OFF;
    float* sprob = sm + SPROB_OFF;
    float* souts = sm + SOUT_OFF;
    float* sacc  = sm + SACC_OFF;

    const int tid = threadIdx.x;
    const int l   = tid & 15;
    const int ph  = (tid >> 4) & 1;
    const int wp  = (tid >> 5) & 1;
    const int fh  = tid >> 6;            // f-half: 0 -> f 0..35, 1 -> f 36..71
    const int posA = 4 * wp + ph;
    const int posB = posA + 2;
    const int f0   = fh * 36;

    const int o    = blockIdx.y;
    const int tile = blockIdx.x;         // 0..511
    const int n    = tile >> 7;
    const int rem  = tile & 127;
    const int y    = rem >> 2;
    const int x0   = (rem & 3) << 3;

    // ---- phase 1a: stage weights (float4, slot swizzle) ----
    {
        const float4* gw = (const float4*)(w + o * 9216);   // 2304 float4s
        float4* sw = (float4*)w_s;
        #pragma unroll
        for (int i = 0; i < 18; i++) {
            int idx = tid + i * 128;
            int f   = idx >> 5;
            int r   = idx & 31;
            int ll  = r >> 1;
            int s   = r & 1;
            sw[f * 32 + ll * 2 + (s ^ ((ll >> 2) & 1))] = gw[idx];
        }
    }
    // ---- phase 1b: stage win patches; thread -> (ppos, p, g-half) ----
    {
        const int ppos = tid & 7;
        const int p    = (tid >> 3) & 7;
        const int gh   = tid >> 6;          // 4 g each
        const int xb   = x0 + ppos - 1;
        bool py[3], px[3];
        #pragma unroll
        for (int k = 0; k < 3; k++) {
            py[k] = (unsigned)(y + k - 1) < 32u;
            px[k] = (unsigned)(xb + k) < 32u;
        }
        const float* xpb = x + ((n * 64 + gh * 32 + p) * 32 + (y - 1)) * 32 + xb;
        float* wd = win_s + ppos * WIN_STRIDE + p + gh * 4 * 9 * 8;
        #pragma unroll
        for (int g = 0; g < 4; g++) {
            #pragma unroll
            for (int kh = 0; kh < 3; kh++) {
                #pragma unroll
                for (int kw = 0; kw < 3; kw++) {
                    float v = 0.0f;
                    if (py[kh] & px[kw])
                        v = xpb[g * 8192 + kh * 32 + kw];
                    wd[(g * 9 + kh * 3 + kw) * 8] = v;
                }
            }
        }
    }
    __syncthreads();

    // ---- phase 1c: priors for both positions, own f-half ----
    float pa[36], pb[36];
    {
        const int b = (l >> 2) & 1;
        const float4* wlo4 = (const float4*)w_s + l * 2 + b;
        const float4* whi4 = (const float4*)w_s + l * 2 + (1 ^ b);
        const float4* xa4  = (const float4*)win_s + posA * (WIN_STRIDE / 4);
        const float4* xb4  = (const float4*)win_s + posB * (WIN_STRIDE / 4);
        #pragma unroll
        for (int f = 0; f < 36; f++) {
            const int F = f0 + f;
            float4 a0 = wlo4[F * 32];
            float4 a1 = whi4[F * 32];
            float4 A0 = xa4[F * 2], A1 = xa4[F * 2 + 1];
            float4 B0 = xb4[F * 2], B1 = xb4[F * 2 + 1];
            pa[f] = dot4(a0, A0) + dot4(a1, A1);
            pb[f] = dot4(a0, B0) + dot4(a1, B1);
        }
    }

    // ---- phase boundary ----
    __syncthreads();

    {
        float* prA = spri + posA * SPRI_POS + l;
        float* prB = spri + posB * SPRI_POS + l;
        #pragma unroll
        for (int f = 0; f < 36; f++) {
            prA[(f0 + f) * SPRI_F] = pa[f];
            prB[(f0 + f) * SPRI_F] = pb[f];
        }
    }
    __syncwarp();

    // ---- phase 2: routing. probs in owner regs (3 per pos) ----
    float pA0 = 1.0f, pA1 = 1.0f, pA2 = 1.0f;
    float pB0 = 1.0f, pB1 = 1.0f, pB2 = 1.0f;
    float outA = 0.0f, outB = 0.0f;
    #pragma unroll
    for (int r = 0; r < 3; r++) {
        float accA = 0.0f, accB = 0.0f;
        if (r == 0) {
            #pragma unroll
            for (int f = 0; f < 36; f++) { accA += pa[f]; accB += pb[f]; }
        } else {
            const float4* prA4 = (const float4*)(sprob + posA * SPROB_POS + fh * 40);
            const float4* prB4 = (const float4*)(sprob + posB * SPROB_POS + fh * 40);
            #pragma unroll
            for (int i = 0; i < 9; i++) {
                float4 qa = prA4[i];
                float4 qb = prB4[i];
                accA += qa.x * pa[4*i] + qa.y * pa[4*i+1] + qa.z * pa[4*i+2] + qa.w * pa[4*i+3];
                accB += qb.x * pb[4*i] + qb.y * pb[4*i+1] + qb.z * pb[4*i+2] + qb.w * pb[4*i+3];
            }
        }
        // combine f-halves across the two fh warps
        const int buf = (r & 1) * 512 / 2;   // 0 or 256
        sacc[buf + fh * 128 + posA * 16 + l] = accA;
        sacc[buf + fh * 128 + posB * 16 + l] = accB;
        __syncthreads();
        accA += sacc[buf + (1 - fh) * 128 + posA * 16 + l];
        accB += sacc[buf + (1 - fh) * 128 + posB * 16 + l];

        float sA = accA * 0.125f, sB = accB * 0.125f;
        float sqA = sA * sA, sqB = sB * sB;
        #pragma unroll
        for (int d = 8; d >= 1; d >>= 1) {
            sqA += __shfl_xor_sync(0xffffffffu, sqA, d);
            sqB += __shfl_xor_sync(0xffffffffu, sqB, d);
        }
        outA = sA * (sqrtf(sqA) / (1.0f + sqA));
        outB = sB * (sqrtf(sqB) / (1.0f + sqB));

        if (r < 2) {
            // both fh warps write identical values -> no cross-warp barrier needed
            souts[posA * 16 + l] = outA;
            souts[posB * 16 + l] = outB;
            __syncwarp();
            const float4* svA = (const float4*)(souts + posA * 16);
            const float4* svB = (const float4*)(souts + posB * 16);
            float4 a0 = svA[0], a1 = svA[1], a2 = svA[2], a3 = svA[3];
            float4 b0 = svB[0], b1 = svB[1], b2 = svB[2], b3 = svB[3];
            // owner lanes: local f = 16j + l (j=2 only l<4)
            #pragma unroll
            for (int j = 0; j < 3; j++) {
                if (j < 2 || l < 4) {
                    const int fl = 16 * j + l;        // local f index
                    const int F  = f0 + fl;           // global f row
                    const float4* qpA = (const float4*)(spri + posA * SPRI_POS + F * SPRI_F);
                    float dA = dot4(qpA[0], a0) + dot4(qpA[1], a1)
                             + dot4(qpA[2], a2) + dot4(qpA[3], a3);
                    float eA = __expf(dA);
                    float nA;
                    if (j == 0)      { pA0 += eA; nA = pA0; }
                    else if (j == 1) { pA1 += eA; nA = pA1; }
                    else             { pA2 += eA; nA = pA2; }
                    sprob[posA * SPROB_POS + fh * 40 + fl] = nA;

                    const float4* qpB = (const float4*)(spri + posB * SPRI_POS + F * SPRI_F);
                    float dB = dot4(qpB[0], b0) + dot4(qpB[1], b1)
                             + dot4(qpB[2], b2) + dot4(qpB[3], b3);
                    float eB = __expf(dB);
                    float nB;
                    if (j == 0)      { pB0 += eB; nB = pB0; }
                    else if (j == 1) { pB1 += eB; nB = pB1; }
                    else             { pB2 += eB; nB = pB2; }
                    sprob[posB * SPROB_POS + fh * 40 + fl] = nB;
                }
            }
            __syncwarp();
        }
    }

    if (fh == 0) {
        float* ob = out + ((n * 128 + o * 16 + l) * 32 + y) * 32 + x0;
        ob[posA] = outA;
        ob[posB] = outB;
    }
}

extern "C" void kernel_launch(void* const* d_in, const int* in_sizes, int n_in,
                              void* d_out, int out_size)
{
    (void)in_sizes; (void)n_in; (void)out_size;
    const float* x = (const float*)d_in[0];
    const float* w = (const float*)d_in[1];
    float* out     = (float*)d_out;

    cudaFuncSetAttribute(caps_kernel, cudaFuncAttributeMaxDynamicSharedMemorySize,
                         SM_FLOATS * 4);
    dim3 grid(512, 8);
    caps_kernel<<<grid, 128, SM_FLOATS * 4>>>(x, w, out);
}

// round 10
// speedup vs baseline: 1.6283x; 1.6097x over previous
#include <cuda_runtime.h>

// CapsuleConv2d fused, round 6: 2 pos/thread + f-split across warps -> 4 CTAs/SM.
// N=4, C=64, H=W=32, O=8, L=16, G=8, P=8, F=72, Ho=Wo=32, NUM_ITERS=3.
// CTA 128 thr = 16 l x 2 ph x 2 wp x 2 fh; covers 8 positions; thread: 2 pos x 36 f.
// grid = (512 tiles, 8 o).
//
// Shared (floats), phase-overlaid, total 13856 = 54.1 KB:
//  phase 1: w_s  [72 f][16 l][2 slot] f4, slot ^ ((l>>2)&1)  @0     (9216)
//           win_s[8 pos](580)[72 f][8 p]                     @9216  (4640)
//  phase 2: spri [8 pos](1456)[72 f](20)[16 l]               @0     (11648)
//           sprob[8 pos](80)[2 fh][40]                       @11648 (640)
//           souts[8 pos][16 l]                               @12288 (128)
//           sacc [2 buf][2 fh][8 pos][16 l]                  @12416 (512)
#define W_S_OFF     0
#define WIN_OFF     9216
#define WIN_STRIDE  580
#define SPRI_OFF    0
#define SPRI_POS    1456
#define SPRI_F      20
#define SPROB_OFF   11648
#define SPROB_POS   80
#define SOUT_OFF    12288
#define SACC_OFF    12416
#define SM_FLOATS   13856

__device__ __forceinline__ float dot4(float4 a, float4 b) {
    return a.x * b.x + a.y * b.y + a.z * b.z + a.w * b.w;
}

__global__ __launch_bounds__(128, 4)
void caps_kernel(const float* __restrict__ x, const float* __restrict__ w,
                 float* __restrict__ out)
{
    extern __shared__ float sm[];
    float* w_s   = sm + W_S_OFF;
    float* win_s = sm + WIN_OFF;
    float* spri  = sm + SPRI_OFF;
    float* sprob = sm + SPROB_OFF;
    float* souts = sm + SOUT_OFF;
    float* sacc  = sm + SACC_OFF;

    const int tid = threadIdx.x;
    const int l   = tid & 15;
    const int ph  = (tid >> 4) & 1;
    const int wp  = (tid >> 5) & 1;
    const int fh  = tid >> 6;            // f-half: 0 -> f 0..35, 1 -> f 36..71
    const int posA = 4 * wp + ph;
    const int posB = posA + 2;
    const int f0   = fh * 36;

    const int o    = blockIdx.y;
    const int tile = blockIdx.x;         // 0..511
    const int n    = tile >> 7;
    const int rem  = tile & 127;
    const int y    = rem >> 2;
    const int x0   = (rem & 3) << 3;

    // ---- phase 1a: stage weights (float4, slot swizzle) ----
    {
        const float4* gw = (const float4*)(w + o * 9216);   // 2304 float4s
        float4* sw = (float4*)w_s;
        #pragma unroll
        for (int i = 0; i < 18; i++) {
            int idx = tid + i * 128;
            int f   = idx >> 5;
            int r   = idx & 31;
            int ll  = r >> 1;
            int s   = r & 1;
            sw[f * 32 + ll * 2 + (s ^ ((ll >> 2) & 1))] = gw[idx];
        }
    }
    // ---- phase 1b: stage win patches; thread -> (ppos, p, g-half) ----
    {
        const int ppos = tid & 7;
        const int p    = (tid >> 3) & 7;
        const int gh   = tid >> 6;          // 4 g each
        const int xb   = x0 + ppos - 1;
        bool py[3], px[3];
        #pragma unroll
        for (int k = 0; k < 3; k++) {
            py[k] = (unsigned)(y + k - 1) < 32u;
            px[k] = (unsigned)(xb + k) < 32u;
        }
        const float* xpb = x + ((n * 64 + gh * 32 + p) * 32 + (y - 1)) * 32 + xb;
        float* wd = win_s + ppos * WIN_STRIDE + p + gh * 4 * 9 * 8;
        #pragma unroll
        for (int g = 0; g < 4; g++) {
            #pragma unroll
            for (int kh = 0; kh < 3; kh++) {
                #pragma unroll
                for (int kw = 0; kw < 3; kw++) {
                    float v = 0.0f;
                    if (py[kh] & px[kw])
                        v = xpb[g * 8192 + kh * 32 + kw];
                    wd[(g * 9 + kh * 3 + kw) * 8] = v;
                }
            }
        }
    }
    __syncthreads();

    // ---- phase 1c: priors for both positions, own f-half ----
    float pa[36], pb[36];
    {
        const int b = (l >> 2) & 1;
        const float4* wlo4 = (const float4*)w_s + l * 2 + b;
        const float4* whi4 = (const float4*)w_s + l * 2 + (1 ^ b);
        const float4* xa4  = (const float4*)win_s + posA * (WIN_STRIDE / 4);
        const float4* xb4  = (const float4*)win_s + posB * (WIN_STRIDE / 4);
        #pragma unroll
        for (int f = 0; f < 36; f++) {
            const int F = f0 + f;
            float4 a0 = wlo4[F * 32];
            float4 a1 = whi4[F * 32];
            float4 A0 = xa4[F * 2], A1 = xa4[F * 2 + 1];
            float4 B0 = xb4[F * 2], B1 = xb4[F * 2 + 1];
            pa[f] = dot4(a0, A0) + dot4(a1, A1);
            pb[f] = dot4(a0, B0) + dot4(a1, B1);
        }
    }

    // ---- phase boundary ----
    __syncthreads();

    {
        float* prA = spri + posA * SPRI_POS + l;
        float* prB = spri + posB * SPRI_POS + l;
        #pragma unroll
        for (int f = 0; f < 36; f++) {
            prA[(f0 + f) * SPRI_F] = pa[f];
            prB[(f0 + f) * SPRI_F] = pb[f];
        }
    }
    __syncwarp();

    // ---- phase 2: routing. probs in owner regs (3 per pos) ----
    float pA0 = 1.0f, pA1 = 1.0f, pA2 = 1.0f;
    float pB0 = 1.0f, pB1 = 1.0f, pB2 = 1.0f;
    float outA = 0.0f, outB = 0.0f;
    #pragma unroll
    for (int r = 0; r < 3; r++) {
        float accA = 0.0f, accB = 0.0f;
        if (r == 0) {
            #pragma unroll
            for (int f = 0; f < 36; f++) { accA += pa[f]; accB += pb[f]; }
        } else {
            const float4* prA4 = (const float4*)(sprob + posA * SPROB_POS + fh * 40);
            const float4* prB4 = (const float4*)(sprob + posB * SPROB_POS + fh * 40);
            #pragma unroll
            for (int i = 0; i < 9; i++) {
                float4 qa = prA4[i];
                float4 qb = prB4[i];
                accA += qa.x * pa[4*i] + qa.y * pa[4*i+1] + qa.z * pa[4*i+2] + qa.w * pa[4*i+3];
                accB += qb.x * pb[4*i] + qb.y * pb[4*i+1] + qb.z * pb[4*i+2] + qb.w * pb[4*i+3];
            }
        }
        // combine f-halves across the two fh warps
        const int buf = (r & 1) * 512 / 2;   // 0 or 256
        sacc[buf + fh * 128 + posA * 16 + l] = accA;
        sacc[buf + fh * 128 + posB * 16 + l] = accB;
        __syncthreads();
        accA += sacc[buf + (1 - fh) * 128 + posA * 16 + l];
        accB += sacc[buf + (1 - fh) * 128 + posB * 16 + l];

        float sA = accA * 0.125f, sB = accB * 0.125f;
        float sqA = sA * sA, sqB = sB * sB;
        #pragma unroll
        for (int d = 8; d >= 1; d >>= 1) {
            sqA += __shfl_xor_sync(0xffffffffu, sqA, d);
            sqB += __shfl_xor_sync(0xffffffffu, sqB, d);
        }
        outA = sA * (sqrtf(sqA) / (1.0f + sqA));
        outB = sB * (sqrtf(sqB) / (1.0f + sqB));

        if (r < 2) {
            // both fh warps write identical values -> no cross-warp barrier needed
            souts[posA * 16 + l] = outA;
            souts[posB * 16 + l] = outB;
            __syncwarp();
            const float4* svA = (const float4*)(souts + posA * 16);
            const float4* svB = (const float4*)(souts + posB * 16);
            float4 a0 = svA[0], a1 = svA[1], a2 = svA[2], a3 = svA[3];
            float4 b0 = svB[0], b1 = svB[1], b2 = svB[2], b3 = svB[3];
            // owner lanes: local f = 16j + l (j=2 only l<4)
            #pragma unroll
            for (int j = 0; j < 3; j++) {
                if (j < 2 || l < 4) {
                    const int fl = 16 * j + l;        // local f index
                    const int F  = f0 + fl;           // global f row
                    const float4* qpA = (const float4*)(spri + posA * SPRI_POS + F * SPRI_F);
                    float dA = dot4(qpA[0], a0) + dot4(qpA[1], a1)
                             + dot4(qpA[2], a2) + dot4(qpA[3], a3);
                    float eA = __expf(dA);
                    float nA;
                    if (j == 0)      { pA0 += eA; nA = pA0; }
                    else if (j == 1) { pA1 += eA; nA = pA1; }
                    else             { pA2 += eA; nA = pA2; }
                    sprob[posA * SPROB_POS + fh * 40 + fl] = nA;

                    const float4* qpB = (const float4*)(spri + posB * SPRI_POS + F * SPRI_F);
                    float dB = dot4(qpB[0], b0) + dot4(qpB[1], b1)
                             + dot4(qpB[2], b2) + dot4(qpB[3], b3);
                    float eB = __expf(dB);
                    float nB;
                    if (j == 0)      { pB0 += eB; nB = pB0; }
                    else if (j == 1) { pB1 += eB; nB = pB1; }
                    else             { pB2 += eB; nB = pB2; }
                    sprob[posB * SPROB_POS + fh * 40 + fl] = nB;
                }
            }
            __syncwarp();
        }
    }

    if (fh == 0) {
        float* ob = out + ((n * 128 + o * 16 + l) * 32 + y) * 32 + x0;
        ob[posA] = outA;
        ob[posB] = outB;
    }
}

extern "C" void kernel_launch(void* const* d_in, const int* in_sizes, int n_in,
                              void* d_out, int out_size)
{
    (void)in_sizes; (void)n_in; (void)out_size;
    const float* x = (const float*)d_in[0];
    const float* w = (const float*)d_in[1];
    float* out     = (float*)d_out;

    cudaFuncSetAttribute(caps_kernel, cudaFuncAttributeMaxDynamicSharedMemorySize,
                         SM_FLOATS * 4);
    dim3 grid(512, 8);
    caps_kernel<<<grid, 128, SM_FLOATS * 4>>>(x, w, out);
}

// round 14
// speedup vs baseline: 1.7991x; 1.1049x over previous
#include <cuda_runtime.h>

// CapsuleConv2d fused, round 14: round-5 (best, 76.5us) + staging-latency overlap.
// Weight LDG.128s issued into registers BEFORE the win LDG/STS stream, so the
// win staging work covers the weight L2 latency; weights STS'd afterwards.
// All compute/layout identical to round 5.
// N=4, C=64, H=W=32, O=8, L=16, G=8, P=8, F=72, Ho=Wo=32, NUM_ITERS=3.
// CTA 128 thr = 16 l x 8 ph; thread: posA=ph, posB=ph+8 (16-pos tile).
// grid = (256 tiles, 8 o).
#define W_S_OFF     0
#define WIN_OFF     9216
#define WIN_STRIDE  580
#define SPRI_OFF    0
#define SPRI_POS    1456
#define SPRI_F      20
#define SPROB_OFF   23296
#define SPROB_POS   80
#define SOUT_OFF    24576
#define SM_FLOATS   24832

__device__ __forceinline__ float dot4(float4 a, float4 b) {
    return a.x * b.x + a.y * b.y + a.z * b.z + a.w * b.w;
}

__global__ __launch_bounds__(128, 2)
void caps_kernel(const float* __restrict__ x, const float* __restrict__ w,
                 float* __restrict__ out)
{
    extern __shared__ float sm[];
    float* w_s   = sm + W_S_OFF;
    float* win_s = sm + WIN_OFF;
    float* spri  = sm + SPRI_OFF;
    float* sprob = sm + SPROB_OFF;
    float* souts = sm + SOUT_OFF;

    const int tid = threadIdx.x;
    const int l   = tid & 15;
    const int ph  = tid >> 4;           // 0..7
    const int posA = ph, posB = ph + 8;

    const int o    = blockIdx.y;
    const int tile = blockIdx.x;        // 0..255
    const int n    = tile >> 6;         // 64 tiles per image
    const int rem  = tile & 63;
    const int y    = rem >> 1;          // output row
    const int x0   = (rem & 1) << 4;    // 0 or 16

    // ---- phase 1a: ISSUE weight LDGs first (fill registers) ----
    float4 wreg[18];
    {
        const float4* gw = (const float4*)(w + o * 9216);   // 2304 float4s
        #pragma unroll
        for (int i = 0; i < 18; i++) wreg[i] = gw[tid + i * 128];
    }

    // ---- phase 1b: win LDG/STS stream (covers weight-LDG latency) ----
    {
        const int ppos = (tid & 7) | ((tid & 64) >> 3);   // warp: 8 ppos x 4 p
        const int p    = (tid >> 3) & 7;
        const int xb   = x0 + ppos - 1;
        bool py[3], px[3];
        #pragma unroll
        for (int k = 0; k < 3; k++) {
            py[k] = (unsigned)(y + k - 1) < 32u;
            px[k] = (unsigned)(xb + k) < 32u;
        }
        const float* xpb = x + ((n * 64 + p) * 32 + (y - 1)) * 32 + xb;
        float* wd = win_s + ppos * WIN_STRIDE + p;
        #pragma unroll
        for (int g = 0; g < 8; g++) {
            #pragma unroll
            for (int kh = 0; kh < 3; kh++) {
                #pragma unroll
                for (int kw = 0; kw < 3; kw++) {
                    float v = 0.0f;
                    if (py[kh] & px[kw])
                        v = xpb[g * 8192 + kh * 32 + kw];
                    wd[(g * 9 + kh * 3 + kw) * 8] = v;
                }
            }
        }
    }

    // ---- phase 1c: STS the prefetched weights (float4, slot swizzle) ----
    {
        float4* sw = (float4*)w_s;
        #pragma unroll
        for (int i = 0; i < 18; i++) {
            int idx = tid + i * 128;
            int f   = idx >> 5;
            int r   = idx & 31;
            int ll  = r >> 1;
            int s   = r & 1;
            sw[f * 32 + ll * 2 + (s ^ ((ll >> 2) & 1))] = wreg[i];
        }
    }
    __syncthreads();

    // ---- phase 1d: priors (fp32 registers) for both positions ----
    float pa[72], pb[72];
    {
        const int b = (l >> 2) & 1;
        const float4* wlo4 = (const float4*)w_s + l * 2 + b;
        const float4* whi4 = (const float4*)w_s + l * 2 + (1 ^ b);
        const float4* xa4  = (const float4*)win_s + posA * (WIN_STRIDE / 4);
        const float4* xb4  = (const float4*)win_s + posB * (WIN_STRIDE / 4);
        #pragma unroll
        for (int f = 0; f < 72; f++) {
            float4 a0 = wlo4[f * 32];
            float4 a1 = whi4[f * 32];
            float4 A0 = xa4[f * 2], A1 = xa4[f * 2 + 1];
            float4 B0 = xb4[f * 2], B1 = xb4[f * 2 + 1];
            pa[f] = dot4(a0, A0) + dot4(a1, A1);
            pb[f] = dot4(a0, B0) + dot4(a1, B1);
        }
    }

    // ---- phase boundary: w_s/win_s dead, overlay becomes live ----
    __syncthreads();

    {
        float* prA = spri + posA * SPRI_POS + l;
        float* prB = spri + posB * SPRI_POS + l;
        #pragma unroll
        for (int f = 0; f < 72; f++) {
            prA[f * SPRI_F] = pa[f];
            prB[f * SPRI_F] = pb[f];
        }
    }
    __syncwarp();

    // ---- phase 2: dynamic routing for both positions ----
    float pA0 = 1.0f, pA1 = 1.0f, pA2 = 1.0f, pA3 = 1.0f, pA4 = 1.0f;
    float pB0 = 1.0f, pB1 = 1.0f, pB2 = 1.0f, pB3 = 1.0f, pB4 = 1.0f;
    float outA = 0.0f, outB = 0.0f;
    #pragma unroll
    for (int r = 0; r < 3; r++) {
        float accA = 0.0f, accB = 0.0f;
        if (r == 0) {
            #pragma unroll
            for (int f = 0; f < 72; f++) { accA += pa[f]; accB += pb[f]; }
        } else {
            const float4* prA4 = (const float4*)(sprob + posA * SPROB_POS);
            const float4* prB4 = (const float4*)(sprob + posB * SPROB_POS);
            #pragma unroll
            for (int i = 0; i < 18; i++) {
                float4 p = prA4[i];
                float4 q = prB4[i];
                accA += p.x * pa[4*i] + p.y * pa[4*i+1] + p.z * pa[4*i+2] + p.w * pa[4*i+3];
                accB += q.x * pb[4*i] + q.y * pb[4*i+1] + q.z * pb[4*i+2] + q.w * pb[4*i+3];
            }
        }
        float sA = accA * 0.125f, sB = accB * 0.125f;
        float sqA = sA * sA, sqB = sB * sB;
        #pragma unroll
        for (int d = 8; d >= 1; d >>= 1) {
            sqA += __shfl_xor_sync(0xffffffffu, sqA, d);
            sqB += __shfl_xor_sync(0xffffffffu, sqB, d);
        }
        outA = sA * (sqrtf(sqA) / (1.0f + sqA));
        outB = sB * (sqrtf(sqB) / (1.0f + sqB));

        if (r < 2) {
            souts[posA * 16 + l] = outA;
            souts[posB * 16 + l] = outB;
            __syncwarp();
            const float4* sov = (const float4*)(souts + posA * 16);
            float4 s0 = sov[0], s1 = sov[1], s2 = sov[2], s3 = sov[3];
            const float4* sov2 = (const float4*)(souts + posB * 16);
            float4 t0 = sov2[0], t1 = sov2[1], t2 = sov2[2], t3 = sov2[3];
            // lane l owns f = l + 16j
            #pragma unroll
            for (int j = 0; j < 5; j++) {
                if (j < 4 || l < 8) {
                    const int fo = l + 16 * j;
                    const float4* qpA = (const float4*)(spri + posA * SPRI_POS + fo * SPRI_F);
                    float dA = dot4(qpA[0], s0) + dot4(qpA[1], s1)
                             + dot4(qpA[2], s2) + dot4(qpA[3], s3);
                    float eA = __expf(dA);
                    float nA;
                    if (j == 0)      { pA0 += eA; nA = pA0; }
                    else if (j == 1) { pA1 += eA; nA = pA1; }
                    else if (j == 2) { pA2 += eA; nA = pA2; }
                    else if (j == 3) { pA3 += eA; nA = pA3; }
                    else             { pA4 += eA; nA = pA4; }
                    sprob[posA * SPROB_POS + fo] = nA;

                    const float4* qpB = (const float4*)(spri + posB * SPRI_POS + fo * SPRI_F);
                    float dB = dot4(qpB[0], t0) + dot4(qpB[1], t1)
                             + dot4(qpB[2], t2) + dot4(qpB[3], t3);
                    float eB = __expf(dB);
                    float nB;
                    if (j == 0)      { pB0 += eB; nB = pB0; }
                    else if (j == 1) { pB1 += eB; nB = pB1; }
                    else if (j == 2) { pB2 += eB; nB = pB2; }
                    else if (j == 3) { pB3 += eB; nB = pB3; }
                    else             { pB4 += eB; nB = pB4; }
                    sprob[posB * SPROB_POS + fo] = nB;
                }
            }
            __syncwarp();
        }
    }

    float* ob = out + ((n * 128 + o * 16 + l) * 32 + y) * 32 + x0;
    ob[posA] = outA;
    ob[posB] = outB;
}

extern "C" void kernel_launch(void* const* d_in, const int* in_sizes, int n_in,
                              void* d_out, int out_size)
{
    (void)in_sizes; (void)n_in; (void)out_size;
    const float* x = (const float*)d_in[0];
    const float* w = (const float*)d_in[1];
    float* out     = (float*)d_out;

    cudaFuncSetAttribute(caps_kernel, cudaFuncAttributeMaxDynamicSharedMemorySize,
                         SM_FLOATS * 4);
    dim3 grid(256, 8);
    caps_kernel<<<grid, 128, SM_FLOATS * 4>>>(x, w, out);
}

// round 15
// speedup vs baseline: 2.0080x; 1.1161x over previous
#include <cuda_runtime.h>

// CapsuleConv2d fused, round 15: f-row ownership — routing phase fully in registers.
// N=4, C=64, H=W=32, O=8, L=16, G=8, P=8, F=72, Ho=Wo=32, NUM_ITERS=3.
// CTA 128 thr = 4 warps; warp w covers pos 4w..4w+3; lane = (slot 0-7, pid 0-3).
// Lane owns pos = 4*warp+pid and f-rows f0..f0+8 (f0 = 9*slot), all 16 l in regs.
// grid = (256 tiles of 16 pos, 8 o).
//
// Shared (floats), single phase, total 18784 = 73.4 KB:
//   w_s  [72 f][132] rows ([l][p] 128 floats + 4 pad)   @0     (9504)
//   win_s[16 pos](580)[72 f][8 p]                       @9504  (9280)
#define WS_ROW     132
#define WIN_OFF    9504
#define WIN_STRIDE 580
#define SM_FLOATS  18784

__device__ __forceinline__ float dot4(float4 a, float4 b) {
    return a.x * b.x + a.y * b.y + a.z * b.z + a.w * b.w;
}

__global__ __launch_bounds__(128, 2)
void caps_kernel(const float* __restrict__ x, const float* __restrict__ w,
                 float* __restrict__ out)
{
    extern __shared__ float sm[];
    float* w_s   = sm;
    float* win_s = sm + WIN_OFF;

    const int tid  = threadIdx.x;
    const int lane = tid & 31;
    const int warp = tid >> 5;
    const int slot = lane & 7;            // f-row group owner
    const int pid  = lane >> 3;           // position within warp
    const int pos  = warp * 4 + pid;      // 0..15
    const int f0   = slot * 9;

    const int o    = blockIdx.y;
    const int tile = blockIdx.x;          // 0..255
    const int n    = tile >> 6;
    const int rem  = tile & 63;
    const int y    = rem >> 1;
    const int x0   = (rem & 1) << 4;

    // ---- stage weights: plain rows, stride 132 floats (33 float4) ----
    {
        const float4* gw = (const float4*)(w + o * 9216);   // 2304 float4s
        float4* sw = (float4*)w_s;                          // row stride 33
        #pragma unroll
        for (int i = 0; i < 18; i++) {
            int idx = tid + i * 128;
            int f   = idx >> 5;
            int r   = idx & 31;
            sw[f * 33 + r] = gw[idx];
        }
    }
    // ---- stage win patches; each thread owns one (ppos, p) ----
    {
        const int ppos = (tid & 7) | ((tid & 64) >> 3);   // 0..15
        const int p    = (tid >> 3) & 7;                  // 0..7
        const int xb   = x0 + ppos - 1;
        bool py[3], px[3];
        #pragma unroll
        for (int k = 0; k < 3; k++) {
            py[k] = (unsigned)(y + k - 1) < 32u;
            px[k] = (unsigned)(xb + k) < 32u;
        }
        const float* xpb = x + ((n * 64 + p) * 32 + (y - 1)) * 32 + xb;
        float* wd = win_s + ppos * WIN_STRIDE + p;
        #pragma unroll
        for (int g = 0; g < 8; g++)
            #pragma unroll
            for (int kh = 0; kh < 3; kh++)
                #pragma unroll
                for (int kw = 0; kw < 3; kw++) {
                    float v = 0.0f;
                    if (py[kh] & px[kw]) v = xpb[g * 8192 + kh * 32 + kw];
                    wd[(g * 9 + kh * 3 + kw) * 8] = v;
                }
    }
    __syncthreads();

    // ---- priors: P[i][l] for own 9 f-rows, own pos ----
    float P[9][16];
    {
        const float4* wv   = (const float4*)w_s;
        const float4* winp = (const float4*)win_s + pos * (WIN_STRIDE / 4);
        #pragma unroll
        for (int i = 0; i < 9; i++) {
            const int f = f0 + i;
            float4 v0 = winp[f * 2];
            float4 v1 = winp[f * 2 + 1];
            #pragma unroll
            for (int l = 0; l < 16; l++) {
                float4 a0 = wv[f * 33 + 2 * l];
                float4 a1 = wv[f * 33 + 2 * l + 1];
                P[i][l] = dot4(a0, v0) + dot4(a1, v1);
            }
        }
    }

    // ---- routing: all state in registers; cross-slot via shuffle allreduce ----
    float probs[9];
    #pragma unroll
    for (int i = 0; i < 9; i++) probs[i] = 1.0f;

    float s[16];
    #pragma unroll
    for (int r = 0; r < 3; r++) {
        // partial weighted sum over own 9 f-rows
        #pragma unroll
        for (int l = 0; l < 16; l++) {
            float acc = 0.0f;
            #pragma unroll
            for (int i = 0; i < 9; i++) acc += probs[i] * P[i][l];
            s[l] = acc;
        }
        // allreduce over the 8 slots of this pos group (xor 1,2,4 stay in-group)
        #pragma unroll
        for (int d = 1; d < 8; d <<= 1) {
            #pragma unroll
            for (int l = 0; l < 16; l++)
                s[l] += __shfl_xor_sync(0xffffffffu, s[l], d);
        }
        // squash (computed redundantly in every lane)
        float sq = 0.0f;
        #pragma unroll
        for (int l = 0; l < 16; l++) { s[l] *= 0.125f; sq += s[l] * s[l]; }
        float factor = sqrtf(sq) / (1.0f + sq);
        #pragma unroll
        for (int l = 0; l < 16; l++) s[l] *= factor;      // s is now the output vec

        if (r < 2) {
            #pragma unroll
            for (int i = 0; i < 9; i++) {
                float d = 0.0f;
                #pragma unroll
                for (int l = 0; l < 16; l++) d += P[i][l] * s[l];
                probs[i] += __expf(d);
            }
        }
    }

    // ---- write: lane emits l = 2*slot, 2*slot+1 for its pos ----
    {
        float* ob = out + ((n * 128 + o * 16) * 32 + y) * 32 + x0 + pos;
        ob[(2 * slot)     * 1024] = s[2 * slot];
        ob[(2 * slot + 1) * 1024] = s[2 * slot + 1];
    }
}

extern "C" void kernel_launch(void* const* d_in, const int* in_sizes, int n_in,
                              void* d_out, int out_size)
{
    (void)in_sizes; (void)n_in; (void)out_size;
    const float* x = (const float*)d_in[0];
    const float* w = (const float*)d_in[1];
    float* out     = (float*)d_out;

    cudaFuncSetAttribute(caps_kernel, cudaFuncAttributeMaxDynamicSharedMemorySize,
                         SM_FLOATS * 4);
    dim3 grid(256, 8);
    caps_kernel<<<grid, 128, SM_FLOATS * 4>>>(x, w, out);
}